// round 13
// baseline (speedup 1.0000x reference)
#include <cuda_runtime.h>

#define B_  4
#define N_  8192
#define C_  64
#define M_  2048
#define NW_ 7
#define QB_ROWS 256
#define NQB 8
#define KST2 36          // K smem row stride in 32-bit words (fp16 c-pairs)
#define VSTW 68          // Vt row stride in 32-bit words (fp16 key-pairs)
#define WST2 36          // W^T smem row stride (fp16 k-pairs)
#define SCALE_LOG2 0.18033688011112042f  // (1/8) * log2(e)

// Q/K/V stored packed fp16x2: [row][32 words], word w = channels (2w, 2w+1)
__device__ unsigned g_Qh[B_*N_*32];
__device__ unsigned g_Kh[B_*N_*32];
__device__ unsigned g_Vh[B_*N_*32];
__device__ float g_O[(long)B_*NW_*M_*C_];
__device__ float g_D[B_*NW_*M_];

__device__ __forceinline__ float ex2(float x) {
    float y; asm("ex2.approx.f32 %0, %1;" : "=f"(y) : "f"(x)); return y;
}
__device__ __forceinline__ void mma16(float d[4], unsigned a0, unsigned a1, unsigned a2,
                                      unsigned a3, unsigned b0, unsigned b1) {
    asm volatile("mma.sync.aligned.m16n8k16.row.col.f32.f16.f16.f32 "
        "{%0,%1,%2,%3},{%4,%5,%6,%7},{%8,%9},{%0,%1,%2,%3};"
        : "+f"(d[0]), "+f"(d[1]), "+f"(d[2]), "+f"(d[3])
        : "r"(a0), "r"(a1), "r"(a2), "r"(a3), "r"(b0), "r"(b1));
}
#define PACK2(D, HI, LO) asm("cvt.rn.f16x2.f32 %0, %1, %2;" : "=r"(D) : "f"(HI), "f"(LO))
#define PRMT(D, A, B, S) asm("prmt.b32 %0, %1, %2, %3;" : "=r"(D) : "r"(A), "r"(B), "n"(S))
#define LDSM4(R0, R1, R2, R3, ADDR) \
    asm volatile("ldmatrix.sync.aligned.m8n8.x4.shared.b16 {%0,%1,%2,%3}, [%4];" \
        : "=r"(R0), "=r"(R1), "=r"(R2), "=r"(R3) : "r"(ADDR))

// ============ Kernel 1: QKV — fp16 tensor cores, packed fp16 out, grid 256 ============
__global__ __launch_bounds__(512) void qkv_kernel(const float* __restrict__ x,
                                                  const float* __restrict__ Wq,
                                                  const float* __restrict__ Wk,
                                                  const float* __restrict__ Wv) {
    extern __shared__ unsigned smw[];   // Wt16[192][WST2]
    const int tid = threadIdx.x;
    const int wid = tid >> 5, lane = tid & 31;
    const int g = lane >> 2, t4 = lane & 3;
    const int rw = wid >> 1;
    const int jh = (wid & 1) * 12;

    const float* Wm[3] = {Wq, Wk, Wv};
    for (int idx = tid; idx < 192*32; idx += 512) {
        int nn = idx >> 5, w = idx & 31;
        const float* Wsrc = Wm[nn >> 6];
        float lo = Wsrc[(2*w    )*64 + (nn & 63)];
        float hi = Wsrc[(2*w + 1)*64 + (nn & 63)];
        unsigned pw; PACK2(pw, hi, lo);
        smw[nn*WST2 + w] = pw;
    }
    __syncthreads();

    const long row0 = (long)blockIdx.x*128 + 16*rw;
    const float* x0 = x + (row0 + g)*C_;
    const float* x1 = x0 + 8*C_;
    unsigned a[4][4];
    #pragma unroll
    for (int kc = 0; kc < 4; kc++) {
        int k0 = 16*kc + 2*t4;
        float2 l0 = *(const float2*)(x0 + k0);
        float2 h0 = *(const float2*)(x0 + k0 + 8);
        float2 l1 = *(const float2*)(x1 + k0);
        float2 h1 = *(const float2*)(x1 + k0 + 8);
        PACK2(a[kc][0], l0.y, l0.x);
        PACK2(a[kc][1], l1.y, l1.x);
        PACK2(a[kc][2], h0.y, h0.x);
        PACK2(a[kc][3], h1.y, h1.x);
    }

    float acc[12][4];
    #pragma unroll
    for (int j = 0; j < 12; j++)
        #pragma unroll
        for (int q = 0; q < 4; q++) acc[j][q] = 0.f;

    #pragma unroll
    for (int kc = 0; kc < 4; kc++) {
        #pragma unroll
        for (int j = 0; j < 12; j++) {
            unsigned b0 = smw[(8*(jh + j) + g)*WST2 + 8*kc + t4];
            unsigned b1 = smw[(8*(jh + j) + g)*WST2 + 8*kc + t4 + 4];
            mma16(acc[j], a[kc][0], a[kc][1], a[kc][2], a[kc][3], b0, b1);
        }
    }

    const long r0 = row0 + g, r1 = r0 + 8;
    #pragma unroll
    for (int j = 0; j < 12; j++) {
        int jj = jh + j;
        unsigned* dst = (jj < 8) ? g_Qh : (jj < 16) ? g_Kh : g_Vh;
        float sc = (jj < 8) ? SCALE_LOG2 : 1.0f;
        int wd = 4*(jj & 7) + t4;
        unsigned w0, w1;
        PACK2(w0, acc[j][1]*sc, acc[j][0]*sc);
        PACK2(w1, acc[j][3]*sc, acc[j][2]*sc);
        dst[r0*32 + wd] = w0;
        dst[r1*32 + wd] = w1;
    }
}

// ==== Kernel 2: flash attention — fp16 mma, ldmatrix B-frags, 128-key steps ====
__global__ __launch_bounds__(256, 1) void attn_kernel() {
    extern __shared__ unsigned smu[];
    unsigned* Ks16 = smu;                 // [128 key][KST2]
    unsigned* Vt32 = smu + 128*KST2;      // [64 c][VSTW]

    const int tid  = threadIdx.x;
    const int wid  = tid >> 5, lane = tid & 31;
    const int g    = lane >> 2, t4 = lane & 3;
    const int mq   = lane >> 3, rr = lane & 7;     // ldmatrix addressing
    const int blk  = blockIdx.x;
    const int qb   = (NQB - 1) - blk / (B_*NW_);   // heaviest first (LPT)
    const int w    = blk % (B_*NW_);
    const int b    = w / NW_, wi = w % NW_;

    int base, r;
    if      (wi < 4) { base = wi*2048;     r = 1; }
    else if (wi < 6) { base = (wi-4)*4096; r = 2; }
    else             { base = 0;           r = 4; }

    const unsigned* Qg = g_Qh + ((long)b*N_ + base)*32;
    const unsigned* Kg = g_Kh + ((long)b*N_ + base)*32;
    const unsigned* Vg = g_Vh + ((long)b*N_ + base)*32;
    const int rsw = r * 32;

    // ldmatrix per-lane base addresses (bytes, shared space)
    const unsigned smbase = (unsigned)__cvta_generic_to_shared(smu);
    const unsigned kaddr0 = smbase + (((mq >> 1)*8 + rr)*KST2)*4 + (mq & 1)*16;
    const unsigned vaddr0 = smbase + 128*KST2*4 + (((mq >> 1)*8 + rr)*VSTW)*4 + (mq & 1)*16;

    // ---- Q fragments: direct packed loads ----
    const int row0 = qb*QB_ROWS + 32*wid;
    unsigned qa[2][4][4];
    #pragma unroll
    for (int mt = 0; mt < 2; mt++) {
        const unsigned* q0 = Qg + (long)(row0 + 16*mt + g)*rsw;
        const unsigned* q1 = q0 + (long)8*rsw;
        #pragma unroll
        for (int kc = 0; kc < 4; kc++) {
            qa[mt][kc][0] = q0[8*kc + t4];
            qa[mt][kc][1] = q1[8*kc + t4];
            qa[mt][kc][2] = q0[8*kc + t4 + 4];
            qa[mt][kc][3] = q1[8*kc + t4 + 4];
        }
    }

    float oacc[2][8][4];
    float mrow[2][2], lrow[2][2];
    #pragma unroll
    for (int mt = 0; mt < 2; mt++) {
        mrow[mt][0] = mrow[mt][1] = -1e30f;
        lrow[mt][0] = lrow[mt][1] = 0.f;
        #pragma unroll
        for (int j = 0; j < 8; j++)
            #pragma unroll
            for (int q = 0; q < 4; q++) oacc[mt][j][q] = 0.f;
    }

    const int nks = 2*qb + 2;
    for (int ks = 0; ks < nks; ks++) {
        __syncthreads();
        // ---- fill K: raw packed copy ----
        #pragma unroll
        for (int i = 0; i < 4; i++) {
            int l = tid + i*256;
            int slot = l >> 3, wg = (l & 7) << 2;
            uint4 kw = *(const uint4*)(Kg + (long)(ks*128 + slot)*rsw + wg);
            *(uint4*)&Ks16[slot*KST2 + wg] = kw;
        }
        // ---- fill V transposed via prmt ----
        #pragma unroll
        for (int i = 0; i < 4; i++) {
            int l = tid + i*256;
            int kp = ((l >> 7) << 3) | (l & 7);
            int cw = (l >> 3) & 15;
            const unsigned* va = Vg + (long)(ks*128 + 2*kp)*rsw + 2*cw;
            uint2 a2 = *(const uint2*)va;
            uint2 b2 = *(const uint2*)(va + rsw);
            unsigned p0, p1, p2, p3;
            PRMT(p0, a2.x, b2.x, 0x5410);
            PRMT(p1, a2.x, b2.x, 0x7632);
            PRMT(p2, a2.y, b2.y, 0x5410);
            PRMT(p3, a2.y, b2.y, 0x7632);
            Vt32[(4*cw+0)*VSTW + kp] = p0;
            Vt32[(4*cw+1)*VSTW + kp] = p1;
            Vt32[(4*cw+2)*VSTW + kp] = p2;
            Vt32[(4*cw+3)*VSTW + kp] = p3;
        }
        __syncthreads();

        #pragma unroll
        for (int half = 0; half < 2; half++) {
            const int kbase = ks*128 + half*64;

            // ---- S = Q K^T : ldmatrix x4 per (kc, j-pair) ----
            float sacc[2][8][4];
            #pragma unroll
            for (int mt = 0; mt < 2; mt++)
                #pragma unroll
                for (int j = 0; j < 8; j++)
                    #pragma unroll
                    for (int q = 0; q < 4; q++) sacc[mt][j][q] = 0.f;

            #pragma unroll
            for (int kc = 0; kc < 4; kc++) {
                #pragma unroll
                for (int jp = 0; jp < 4; jp++) {
                    unsigned b00, b01, b10, b11;
                    unsigned addr = kaddr0 + (((half*64 + 16*jp)*KST2 + 8*kc) << 2);
                    LDSM4(b00, b01, b10, b11, addr);
                    mma16(sacc[0][2*jp  ], qa[0][kc][0], qa[0][kc][1], qa[0][kc][2], qa[0][kc][3], b00, b01);
                    mma16(sacc[1][2*jp  ], qa[1][kc][0], qa[1][kc][1], qa[1][kc][2], qa[1][kc][3], b00, b01);
                    mma16(sacc[0][2*jp+1], qa[0][kc][0], qa[0][kc][1], qa[0][kc][2], qa[0][kc][3], b10, b11);
                    mma16(sacc[1][2*jp+1], qa[1][kc][0], qa[1][kc][1], qa[1][kc][2], qa[1][kc][3], b10, b11);
                }
            }

            // ---- causal mask ----
            if (ks >= 2*qb) {
                #pragma unroll
                for (int mt = 0; mt < 2; mt++) {
                    int r0_ = row0 + 16*mt + g, r1_ = r0_ + 8;
                    #pragma unroll
                    for (int j = 0; j < 8; j++) {
                        int k0 = kbase + 8*j + 2*t4, k1 = k0 + 1;
                        if (k0 > r0_) sacc[mt][j][0] = -1e30f;
                        if (k1 > r0_) sacc[mt][j][1] = -1e30f;
                        if (k0 > r1_) sacc[mt][j][2] = -1e30f;
                        if (k1 > r1_) sacc[mt][j][3] = -1e30f;
                    }
                }
            }

            // ---- online softmax (log2 domain) ----
            #pragma unroll
            for (int mt = 0; mt < 2; mt++) {
                float rm0 = -1e30f, rm1 = -1e30f;
                #pragma unroll
                for (int j = 0; j < 8; j++) {
                    rm0 = fmaxf(rm0, fmaxf(sacc[mt][j][0], sacc[mt][j][1]));
                    rm1 = fmaxf(rm1, fmaxf(sacc[mt][j][2], sacc[mt][j][3]));
                }
                rm0 = fmaxf(rm0, __shfl_xor_sync(0xffffffffu, rm0, 1));
                rm0 = fmaxf(rm0, __shfl_xor_sync(0xffffffffu, rm0, 2));
                rm1 = fmaxf(rm1, __shfl_xor_sync(0xffffffffu, rm1, 1));
                rm1 = fmaxf(rm1, __shfl_xor_sync(0xffffffffu, rm1, 2));
                float mn0 = fmaxf(mrow[mt][0], rm0), mn1 = fmaxf(mrow[mt][1], rm1);
                float c0 = ex2(mrow[mt][0] - mn0),   c1 = ex2(mrow[mt][1] - mn1);
                mrow[mt][0] = mn0; mrow[mt][1] = mn1;
                float rs0 = 0.f, rs1 = 0.f;
                #pragma unroll
                for (int j = 0; j < 8; j++) {
                    float p0 = ex2(sacc[mt][j][0] - mn0); rs0 += p0; sacc[mt][j][0] = p0;
                    float p1 = ex2(sacc[mt][j][1] - mn0); rs0 += p1; sacc[mt][j][1] = p1;
                    float p2 = ex2(sacc[mt][j][2] - mn1); rs1 += p2; sacc[mt][j][2] = p2;
                    float p3 = ex2(sacc[mt][j][3] - mn1); rs1 += p3; sacc[mt][j][3] = p3;
                }
                rs0 += __shfl_xor_sync(0xffffffffu, rs0, 1);
                rs0 += __shfl_xor_sync(0xffffffffu, rs0, 2);
                rs1 += __shfl_xor_sync(0xffffffffu, rs1, 1);
                rs1 += __shfl_xor_sync(0xffffffffu, rs1, 2);
                lrow[mt][0] = lrow[mt][0]*c0 + rs0;
                lrow[mt][1] = lrow[mt][1]*c1 + rs1;
                #pragma unroll
                for (int jv = 0; jv < 8; jv++) {
                    oacc[mt][jv][0] *= c0; oacc[mt][jv][1] *= c0;
                    oacc[mt][jv][2] *= c1; oacc[mt][jv][3] *= c1;
                }
            }

            // ---- O += P V : ldmatrix x4 per (u, jv-pair) ----
            #pragma unroll
            for (int u = 0; u < 4; u++) {
                unsigned a00, a01, a02, a03, a10, a11, a12, a13;
                PACK2(a00, sacc[0][2*u  ][1], sacc[0][2*u  ][0]);
                PACK2(a01, sacc[0][2*u  ][3], sacc[0][2*u  ][2]);
                PACK2(a02, sacc[0][2*u+1][1], sacc[0][2*u+1][0]);
                PACK2(a03, sacc[0][2*u+1][3], sacc[0][2*u+1][2]);
                PACK2(a10, sacc[1][2*u  ][1], sacc[1][2*u  ][0]);
                PACK2(a11, sacc[1][2*u  ][3], sacc[1][2*u  ][2]);
                PACK2(a12, sacc[1][2*u+1][1], sacc[1][2*u+1][0]);
                PACK2(a13, sacc[1][2*u+1][3], sacc[1][2*u+1][2]);
                const int kpb = half*32 + 8*u;
                #pragma unroll
                for (int jvp = 0; jvp < 4; jvp++) {
                    unsigned b00, b01, b10, b11;
                    unsigned addr = vaddr0 + ((16*jvp*VSTW + kpb) << 2);
                    LDSM4(b00, b01, b10, b11, addr);
                    mma16(oacc[0][2*jvp  ], a00, a01, a02, a03, b00, b01);
                    mma16(oacc[1][2*jvp  ], a10, a11, a12, a13, b00, b01);
                    mma16(oacc[0][2*jvp+1], a00, a01, a02, a03, b10, b11);
                    mma16(oacc[1][2*jvp+1], a10, a11, a12, a13, b10, b11);
                }
            }
        }
    }

    // ---- epilogue ----
    float* Og = g_O + (long)(b*NW_ + wi)*M_*C_;
    float* Dg = g_D + (long)(b*NW_ + wi)*M_;
    #pragma unroll
    for (int mt = 0; mt < 2; mt++) {
        int r0_ = row0 + 16*mt + g, r1_ = r0_ + 8;
        float i0 = 1.0f / lrow[mt][0], i1 = 1.0f / lrow[mt][1];
        #pragma unroll
        for (int jv = 0; jv < 8; jv++) {
            *(float2*)&Og[(long)r0_*C_ + 8*jv + 2*t4] =
                make_float2(oacc[mt][jv][0]*i0, oacc[mt][jv][1]*i0);
            *(float2*)&Og[(long)r1_*C_ + 8*jv + 2*t4] =
                make_float2(oacc[mt][jv][2]*i1, oacc[mt][jv][3]*i1);
        }
        if (t4 == 0) {
            Dg[r0_] = lrow[mt][0] * ex2(mrow[mt][0]);
            Dg[r1_] = lrow[mt][1] * ex2(mrow[mt][1]);
        }
    }
}

// ============================ Kernel 3: mix ============================
__global__ __launch_bounds__(256) void mix_kernel(float* __restrict__ out) {
    const int tid = threadIdx.x;
    const int c = tid & 63;
    const int gp = blockIdx.x*4 + (tid >> 6);
    const int b = gp >> 13;
    const int p = gp & (N_-1);

    int w0 = p >> 11, r0 = p & 2047;
    long i0 = (long)(b*NW_ + w0)*M_ + r0;
    float d0 = g_D[i0];
    float dsum = d0;
    float num  = d0 * g_O[i0*C_ + c];

    if ((p & 1) == 0) {
        int w1 = 4 + (p >> 12), r1 = (p & 4095) >> 1;
        long i1 = (long)(b*NW_ + w1)*M_ + r1;
        float d1 = g_D[i1];
        dsum += d1;
        num  += d1 * g_O[i1*C_ + c];
    }
    if ((p & 3) == 0) {
        long i2 = (long)(b*NW_ + 6)*M_ + (p >> 2);
        float d2 = g_D[i2];
        dsum += d2;
        num  += d2 * g_O[i2*C_ + c];
    }
    out[((long)b*N_ + p)*C_ + c] = num / dsum;
}

// =======================================================================
extern "C" void kernel_launch(void* const* d_in, const int* in_sizes, int n_in,
                              void* d_out, int out_size) {
    (void)in_sizes; (void)n_in; (void)out_size;
    const float* x  = (const float*)d_in[0];
    const float* Wq = (const float*)d_in[1];
    const float* Wk = (const float*)d_in[2];
    const float* Wv = (const float*)d_in[3];
    float* out = (float*)d_out;

    const int smem1 = 192*WST2*4;                      // 27648 B
    const int smem2 = (128*KST2 + 64*VSTW) * 4;        // 35840 B
    cudaFuncSetAttribute(qkv_kernel,  cudaFuncAttributeMaxDynamicSharedMemorySize, smem1);
    cudaFuncSetAttribute(attn_kernel, cudaFuncAttributeMaxDynamicSharedMemorySize, smem2);

    qkv_kernel<<<(B_*N_)/128, 512, smem1>>>(x, Wq, Wk, Wv);
    attn_kernel<<<NQB * B_ * NW_, 256, smem2>>>();
    mix_kernel<<<(B_*N_)/4, 256>>>(out);
}

// round 14
// speedup vs baseline: 1.1040x; 1.1040x over previous
#include <cuda_runtime.h>

#define B_  4
#define N_  8192
#define C_  64
#define M_  2048
#define NW_ 7
#define QB_ROWS 256
#define NQB 8
#define KST2 36          // K smem row stride in 32-bit words (fp16 c-pairs)
#define VSTW 68          // Vt row stride in 32-bit words (fp16 key-pairs)
#define WST2 36          // W^T smem row stride (fp16 k-pairs)
#define SCALE_LOG2 0.18033688011112042f  // (1/8) * log2(e)

// Q/K/V packed fp16x2: [row][32 words], word w = channels (2w, 2w+1)
__device__ unsigned g_Qh[B_*N_*32];
__device__ unsigned g_Kh[B_*N_*32];
__device__ unsigned g_Vh[B_*N_*32];
__device__ float g_O[(long)B_*NW_*M_*C_];
__device__ float g_D[B_*NW_*M_];

__device__ __forceinline__ float ex2(float x) {
    float y; asm("ex2.approx.f32 %0, %1;" : "=f"(y) : "f"(x)); return y;
}
__device__ __forceinline__ void mma16(float d[4], unsigned a0, unsigned a1, unsigned a2,
                                      unsigned a3, unsigned b0, unsigned b1) {
    asm volatile("mma.sync.aligned.m16n8k16.row.col.f32.f16.f16.f32 "
        "{%0,%1,%2,%3},{%4,%5,%6,%7},{%8,%9},{%0,%1,%2,%3};"
        : "+f"(d[0]), "+f"(d[1]), "+f"(d[2]), "+f"(d[3])
        : "r"(a0), "r"(a1), "r"(a2), "r"(a3), "r"(b0), "r"(b1));
}
#define PACK2(D, HI, LO) asm("cvt.rn.f16x2.f32 %0, %1, %2;" : "=r"(D) : "f"(HI), "f"(LO))
#define PRMT(D, A, B, S) asm("prmt.b32 %0, %1, %2, %3;" : "=r"(D) : "r"(A), "r"(B), "n"(S))
#define LDSM4(R0, R1, R2, R3, ADDR) \
    asm volatile("ldmatrix.sync.aligned.m8n8.x4.shared.b16 {%0,%1,%2,%3}, [%4];" \
        : "=r"(R0), "=r"(R1), "=r"(R2), "=r"(R3) : "r"(ADDR))

// ====== Kernel 1: QKV — fp16 TC, grid 128 (R12 shape), coalesced W staging ======
__global__ __launch_bounds__(512) void qkv_kernel(const float* __restrict__ x,
                                                  const float* __restrict__ Wq,
                                                  const float* __restrict__ Wk,
                                                  const float* __restrict__ Wv) {
    extern __shared__ unsigned smw[];   // Wt16[192][WST2]
    const int tid = threadIdx.x;
    const int wid = tid >> 5, lane = tid & 31;
    const int g = lane >> 2, t4 = lane & 3;
    const int rw = wid >> 1;
    const int jh = (wid & 1) * 12;

    // coalesced staging: consecutive lanes -> consecutive output cols nn
    const float* Wm[3] = {Wq, Wk, Wv};
    for (int idx = tid; idx < 192*32; idx += 512) {
        int w = idx / 192, nn = idx % 192;
        const float* Wsrc = Wm[nn >> 6];
        float lo = Wsrc[(2*w    )*64 + (nn & 63)];
        float hi = Wsrc[(2*w + 1)*64 + (nn & 63)];
        unsigned pw; PACK2(pw, hi, lo);
        smw[nn*WST2 + w] = pw;
    }
    __syncthreads();

    #pragma unroll
    for (int it = 0; it < 2; it++) {
        const long row0 = (long)blockIdx.x*256 + it*128 + 16*rw;
        const float* x0 = x + (row0 + g)*C_;
        const float* x1 = x0 + 8*C_;
        unsigned a[4][4];
        #pragma unroll
        for (int kc = 0; kc < 4; kc++) {
            int k0 = 16*kc + 2*t4;
            float2 l0 = *(const float2*)(x0 + k0);
            float2 h0 = *(const float2*)(x0 + k0 + 8);
            float2 l1 = *(const float2*)(x1 + k0);
            float2 h1 = *(const float2*)(x1 + k0 + 8);
            PACK2(a[kc][0], l0.y, l0.x);
            PACK2(a[kc][1], l1.y, l1.x);
            PACK2(a[kc][2], h0.y, h0.x);
            PACK2(a[kc][3], h1.y, h1.x);
        }

        float acc[12][4];
        #pragma unroll
        for (int j = 0; j < 12; j++)
            #pragma unroll
            for (int q = 0; q < 4; q++) acc[j][q] = 0.f;

        #pragma unroll
        for (int kc = 0; kc < 4; kc++) {
            #pragma unroll
            for (int j = 0; j < 12; j++) {
                unsigned b0 = smw[(8*(jh + j) + g)*WST2 + 8*kc + t4];
                unsigned b1 = smw[(8*(jh + j) + g)*WST2 + 8*kc + t4 + 4];
                mma16(acc[j], a[kc][0], a[kc][1], a[kc][2], a[kc][3], b0, b1);
            }
        }

        const long r0 = row0 + g, r1 = r0 + 8;
        #pragma unroll
        for (int j = 0; j < 12; j++) {
            int jj = jh + j;
            unsigned* dst = (jj < 8) ? g_Qh : (jj < 16) ? g_Kh : g_Vh;
            float sc = (jj < 8) ? SCALE_LOG2 : 1.0f;
            int wd = 4*(jj & 7) + t4;
            unsigned w0, w1;
            PACK2(w0, acc[j][1]*sc, acc[j][0]*sc);
            PACK2(w1, acc[j][3]*sc, acc[j][2]*sc);
            dst[r0*32 + wd] = w0;
            dst[r1*32 + wd] = w1;
        }
    }
}

// ==== Kernel 2: flash attention — 512 thr / 16 warps / 16 rows each, LDSM B-frags ====
__global__ __launch_bounds__(512, 1) void attn_kernel() {
    extern __shared__ unsigned smu[];
    unsigned* Ks16 = smu;                 // [128 key][KST2]
    unsigned* Vt32 = smu + 128*KST2;      // [64 c][VSTW]

    const int tid  = threadIdx.x;
    const int wid  = tid >> 5, lane = tid & 31;
    const int g    = lane >> 2, t4 = lane & 3;
    const int mq   = lane >> 3, rr = lane & 7;
    const int blk  = blockIdx.x;
    const int qb   = (NQB - 1) - blk / (B_*NW_);   // heaviest first (LPT)
    const int w    = blk % (B_*NW_);
    const int b    = w / NW_, wi = w % NW_;

    int base, r;
    if      (wi < 4) { base = wi*2048;     r = 1; }
    else if (wi < 6) { base = (wi-4)*4096; r = 2; }
    else             { base = 0;           r = 4; }

    const unsigned* Qg = g_Qh + ((long)b*N_ + base)*32;
    const unsigned* Kg = g_Kh + ((long)b*N_ + base)*32;
    const unsigned* Vg = g_Vh + ((long)b*N_ + base)*32;
    const int rsw = r * 32;

    const unsigned smbase = (unsigned)__cvta_generic_to_shared(smu);
    const unsigned kaddr0 = smbase + (((mq >> 1)*8 + rr)*KST2)*4 + (mq & 1)*16;
    const unsigned vaddr0 = smbase + 128*KST2*4 + (((mq >> 1)*8 + rr)*VSTW)*4 + (mq & 1)*16;

    // ---- Q fragments: 16 rows per warp ----
    const int row0 = qb*QB_ROWS + 16*wid;
    unsigned qa[4][4];
    {
        const unsigned* q0 = Qg + (long)(row0 + g)*rsw;
        const unsigned* q1 = q0 + (long)8*rsw;
        #pragma unroll
        for (int kc = 0; kc < 4; kc++) {
            qa[kc][0] = q0[8*kc + t4];
            qa[kc][1] = q1[8*kc + t4];
            qa[kc][2] = q0[8*kc + t4 + 4];
            qa[kc][3] = q1[8*kc + t4 + 4];
        }
    }

    float oacc[8][4];
    float m0 = -1e30f, m1 = -1e30f, l0v = 0.f, l1v = 0.f;
    #pragma unroll
    for (int j = 0; j < 8; j++)
        #pragma unroll
        for (int q = 0; q < 4; q++) oacc[j][q] = 0.f;

    const int nks = 2*qb + 2;
    for (int ks = 0; ks < nks; ks++) {
        __syncthreads();
        // ---- fill K: raw packed copy (1024 uint4 over 512 threads) ----
        #pragma unroll
        for (int i = 0; i < 2; i++) {
            int l = tid + i*512;
            int slot = l >> 3, wg = (l & 7) << 2;
            uint4 kw = *(const uint4*)(Kg + (long)(ks*128 + slot)*rsw + wg);
            *(uint4*)&Ks16[slot*KST2 + wg] = kw;
        }
        // ---- fill V transposed via prmt ----
        #pragma unroll
        for (int i = 0; i < 2; i++) {
            int l = tid + i*512;
            int kp = ((l >> 7) << 3) | (l & 7);
            int cw = (l >> 3) & 15;
            const unsigned* va = Vg + (long)(ks*128 + 2*kp)*rsw + 2*cw;
            uint2 a2 = *(const uint2*)va;
            uint2 b2 = *(const uint2*)(va + rsw);
            unsigned p0, p1, p2, p3;
            PRMT(p0, a2.x, b2.x, 0x5410);
            PRMT(p1, a2.x, b2.x, 0x7632);
            PRMT(p2, a2.y, b2.y, 0x5410);
            PRMT(p3, a2.y, b2.y, 0x7632);
            Vt32[(4*cw+0)*VSTW + kp] = p0;
            Vt32[(4*cw+1)*VSTW + kp] = p1;
            Vt32[(4*cw+2)*VSTW + kp] = p2;
            Vt32[(4*cw+3)*VSTW + kp] = p3;
        }
        __syncthreads();

        #pragma unroll
        for (int half = 0; half < 2; half++) {
            const int kbase = ks*128 + half*64;

            // ---- S = Q K^T (ldmatrix x4 per (kc, j-pair)) ----
            float sacc[8][4];
            #pragma unroll
            for (int j = 0; j < 8; j++)
                #pragma unroll
                for (int q = 0; q < 4; q++) sacc[j][q] = 0.f;

            #pragma unroll
            for (int kc = 0; kc < 4; kc++) {
                #pragma unroll
                for (int jp = 0; jp < 4; jp++) {
                    unsigned b00, b01, b10, b11;
                    unsigned addr = kaddr0 + (((half*64 + 16*jp)*KST2 + 8*kc) << 2);
                    LDSM4(b00, b01, b10, b11, addr);
                    mma16(sacc[2*jp  ], qa[kc][0], qa[kc][1], qa[kc][2], qa[kc][3], b00, b01);
                    mma16(sacc[2*jp+1], qa[kc][0], qa[kc][1], qa[kc][2], qa[kc][3], b10, b11);
                }
            }

            // ---- causal mask ----
            if (ks >= 2*qb) {
                int r0_ = row0 + g, r1_ = r0_ + 8;
                #pragma unroll
                for (int j = 0; j < 8; j++) {
                    int k0 = kbase + 8*j + 2*t4, k1 = k0 + 1;
                    if (k0 > r0_) sacc[j][0] = -1e30f;
                    if (k1 > r0_) sacc[j][1] = -1e30f;
                    if (k0 > r1_) sacc[j][2] = -1e30f;
                    if (k1 > r1_) sacc[j][3] = -1e30f;
                }
            }

            // ---- online softmax (log2 domain) ----
            {
                float rm0 = -1e30f, rm1 = -1e30f;
                #pragma unroll
                for (int j = 0; j < 8; j++) {
                    rm0 = fmaxf(rm0, fmaxf(sacc[j][0], sacc[j][1]));
                    rm1 = fmaxf(rm1, fmaxf(sacc[j][2], sacc[j][3]));
                }
                rm0 = fmaxf(rm0, __shfl_xor_sync(0xffffffffu, rm0, 1));
                rm0 = fmaxf(rm0, __shfl_xor_sync(0xffffffffu, rm0, 2));
                rm1 = fmaxf(rm1, __shfl_xor_sync(0xffffffffu, rm1, 1));
                rm1 = fmaxf(rm1, __shfl_xor_sync(0xffffffffu, rm1, 2));
                float mn0 = fmaxf(m0, rm0), mn1 = fmaxf(m1, rm1);
                float c0 = ex2(m0 - mn0),   c1 = ex2(m1 - mn1);
                m0 = mn0; m1 = mn1;
                float rs0 = 0.f, rs1 = 0.f;
                #pragma unroll
                for (int j = 0; j < 8; j++) {
                    float p0 = ex2(sacc[j][0] - mn0); rs0 += p0; sacc[j][0] = p0;
                    float p1 = ex2(sacc[j][1] - mn0); rs0 += p1; sacc[j][1] = p1;
                    float p2 = ex2(sacc[j][2] - mn1); rs1 += p2; sacc[j][2] = p2;
                    float p3 = ex2(sacc[j][3] - mn1); rs1 += p3; sacc[j][3] = p3;
                }
                rs0 += __shfl_xor_sync(0xffffffffu, rs0, 1);
                rs0 += __shfl_xor_sync(0xffffffffu, rs0, 2);
                rs1 += __shfl_xor_sync(0xffffffffu, rs1, 1);
                rs1 += __shfl_xor_sync(0xffffffffu, rs1, 2);
                l0v = l0v*c0 + rs0;
                l1v = l1v*c1 + rs1;
                #pragma unroll
                for (int jv = 0; jv < 8; jv++) {
                    oacc[jv][0] *= c0; oacc[jv][1] *= c0;
                    oacc[jv][2] *= c1; oacc[jv][3] *= c1;
                }
            }

            // ---- O += P V (ldmatrix x4 per (u, jv-pair)) ----
            #pragma unroll
            for (int u = 0; u < 4; u++) {
                unsigned a0, a1, a2, a3;
                PACK2(a0, sacc[2*u  ][1], sacc[2*u  ][0]);
                PACK2(a1, sacc[2*u  ][3], sacc[2*u  ][2]);
                PACK2(a2, sacc[2*u+1][1], sacc[2*u+1][0]);
                PACK2(a3, sacc[2*u+1][3], sacc[2*u+1][2]);
                const int kpb = half*32 + 8*u;
                #pragma unroll
                for (int jvp = 0; jvp < 4; jvp++) {
                    unsigned b00, b01, b10, b11;
                    unsigned addr = vaddr0 + ((16*jvp*VSTW + kpb) << 2);
                    LDSM4(b00, b01, b10, b11, addr);
                    mma16(oacc[2*jvp  ], a0, a1, a2, a3, b00, b01);
                    mma16(oacc[2*jvp+1], a0, a1, a2, a3, b10, b11);
                }
            }
        }
    }

    // ---- epilogue ----
    float* Og = g_O + (long)(b*NW_ + wi)*M_*C_;
    float* Dg = g_D + (long)(b*NW_ + wi)*M_;
    {
        int r0_ = row0 + g, r1_ = r0_ + 8;
        float i0 = 1.0f / l0v, i1 = 1.0f / l1v;
        #pragma unroll
        for (int jv = 0; jv < 8; jv++) {
            *(float2*)&Og[(long)r0_*C_ + 8*jv + 2*t4] =
                make_float2(oacc[jv][0]*i0, oacc[jv][1]*i0);
            *(float2*)&Og[(long)r1_*C_ + 8*jv + 2*t4] =
                make_float2(oacc[jv][2]*i1, oacc[jv][3]*i1);
        }
        if (t4 == 0) {
            Dg[r0_] = l0v * ex2(m0);
            Dg[r1_] = l1v * ex2(m1);
        }
    }
}

// ============================ Kernel 3: mix ============================
__global__ __launch_bounds__(256) void mix_kernel(float* __restrict__ out) {
    const int tid = threadIdx.x;
    const int c = tid & 63;
    const int gp = blockIdx.x*4 + (tid >> 6);
    const int b = gp >> 13;
    const int p = gp & (N_-1);

    int w0 = p >> 11, r0 = p & 2047;
    long i0 = (long)(b*NW_ + w0)*M_ + r0;
    float d0 = g_D[i0];
    float dsum = d0;
    float num  = d0 * g_O[i0*C_ + c];

    if ((p & 1) == 0) {
        int w1 = 4 + (p >> 12), r1 = (p & 4095) >> 1;
        long i1 = (long)(b*NW_ + w1)*M_ + r1;
        float d1 = g_D[i1];
        dsum += d1;
        num  += d1 * g_O[i1*C_ + c];
    }
    if ((p & 3) == 0) {
        long i2 = (long)(b*NW_ + 6)*M_ + (p >> 2);
        float d2 = g_D[i2];
        dsum += d2;
        num  += d2 * g_O[i2*C_ + c];
    }
    out[((long)b*N_ + p)*C_ + c] = num / dsum;
}

// =======================================================================
extern "C" void kernel_launch(void* const* d_in, const int* in_sizes, int n_in,
                              void* d_out, int out_size) {
    (void)in_sizes; (void)n_in; (void)out_size;
    const float* x  = (const float*)d_in[0];
    const float* Wq = (const float*)d_in[1];
    const float* Wk = (const float*)d_in[2];
    const float* Wv = (const float*)d_in[3];
    float* out = (float*)d_out;

    const int smem1 = 192*WST2*4;                      // 27648 B
    const int smem2 = (128*KST2 + 64*VSTW) * 4;        // 35840 B
    cudaFuncSetAttribute(qkv_kernel,  cudaFuncAttributeMaxDynamicSharedMemorySize, smem1);
    cudaFuncSetAttribute(attn_kernel, cudaFuncAttributeMaxDynamicSharedMemorySize, smem2);

    qkv_kernel<<<(B_*N_)/256, 512, smem1>>>(x, Wq, Wk, Wv);
    attn_kernel<<<NQB * B_ * NW_, 512, smem2>>>();
    mix_kernel<<<(B_*N_)/4, 256>>>(out);
}

// round 15
// speedup vs baseline: 1.2682x; 1.1488x over previous
#include <cuda_runtime.h>

#define B_  4
#define N_  8192
#define C_  64
#define M_  2048
#define NW_ 7
#define QB_ROWS 256
#define NQB 8
#define KST3 36          // K/V smem row stride in 32-bit words
#define WST2 36
#define SSBW (128*KST3*2)          // words per stage (K + V)
#define SCALE_LOG2 0.18033688011112042f  // (1/8) * log2(e)

__device__ unsigned g_Qh[B_*N_*32];
__device__ unsigned g_Kh[B_*N_*32];
__device__ unsigned g_Vh[B_*N_*32];
__device__ float g_O[(long)B_*NW_*M_*C_];
__device__ float g_D[B_*NW_*M_];

__device__ __forceinline__ float ex2(float x) {
    float y; asm("ex2.approx.f32 %0, %1;" : "=f"(y) : "f"(x)); return y;
}
__device__ __forceinline__ void mma16(float d[4], unsigned a0, unsigned a1, unsigned a2,
                                      unsigned a3, unsigned b0, unsigned b1) {
    asm volatile("mma.sync.aligned.m16n8k16.row.col.f32.f16.f16.f32 "
        "{%0,%1,%2,%3},{%4,%5,%6,%7},{%8,%9},{%0,%1,%2,%3};"
        : "+f"(d[0]), "+f"(d[1]), "+f"(d[2]), "+f"(d[3])
        : "r"(a0), "r"(a1), "r"(a2), "r"(a3), "r"(b0), "r"(b1));
}
#define PACK2(D, HI, LO) asm("cvt.rn.f16x2.f32 %0, %1, %2;" : "=r"(D) : "f"(HI), "f"(LO))
#define LDSM4(R0, R1, R2, R3, ADDR) \
    asm volatile("ldmatrix.sync.aligned.m8n8.x4.shared.b16 {%0,%1,%2,%3}, [%4];" \
        : "=r"(R0), "=r"(R1), "=r"(R2), "=r"(R3) : "r"(ADDR))
#define LDSM4T(R0, R1, R2, R3, ADDR) \
    asm volatile("ldmatrix.sync.aligned.m8n8.x4.trans.shared.b16 {%0,%1,%2,%3}, [%4];" \
        : "=r"(R0), "=r"(R1), "=r"(R2), "=r"(R3) : "r"(ADDR))
#define CPA16(DST, SRC) \
    asm volatile("cp.async.cg.shared.global [%0], [%1], 16;" :: "r"(DST), "l"(SRC))

// ====== Kernel 1: QKV — fp16 TC, grid 128, x-loads hoisted over W staging ======
__global__ __launch_bounds__(512) void qkv_kernel(const float* __restrict__ x,
                                                  const float* __restrict__ Wq,
                                                  const float* __restrict__ Wk,
                                                  const float* __restrict__ Wv) {
    extern __shared__ unsigned smw[];   // Wt16[192][WST2]
    const int tid = threadIdx.x;
    const int wid = tid >> 5, lane = tid & 31;
    const int g = lane >> 2, t4 = lane & 3;
    const int rw = wid >> 1;
    const int jh = (wid & 1) * 12;

    // hoisted x loads for iteration 0 (overlap W staging latency)
    unsigned a[4][4];
    {
        const long row0 = (long)blockIdx.x*256 + 16*rw;
        const float* x0 = x + (row0 + g)*C_;
        const float* x1 = x0 + 8*C_;
        #pragma unroll
        for (int kc = 0; kc < 4; kc++) {
            int k0 = 16*kc + 2*t4;
            float2 l0 = *(const float2*)(x0 + k0);
            float2 h0 = *(const float2*)(x0 + k0 + 8);
            float2 l1 = *(const float2*)(x1 + k0);
            float2 h1 = *(const float2*)(x1 + k0 + 8);
            PACK2(a[kc][0], l0.y, l0.x);
            PACK2(a[kc][1], l1.y, l1.x);
            PACK2(a[kc][2], h0.y, h0.x);
            PACK2(a[kc][3], h1.y, h1.x);
        }
    }

    const float* Wm[3] = {Wq, Wk, Wv};
    for (int idx = tid; idx < 192*32; idx += 512) {
        int w = idx / 192, nn = idx % 192;
        const float* Wsrc = Wm[nn >> 6];
        float lo = Wsrc[(2*w    )*64 + (nn & 63)];
        float hi = Wsrc[(2*w + 1)*64 + (nn & 63)];
        unsigned pw; PACK2(pw, hi, lo);
        smw[nn*WST2 + w] = pw;
    }
    __syncthreads();

    #pragma unroll
    for (int it = 0; it < 2; it++) {
        const long row0 = (long)blockIdx.x*256 + it*128 + 16*rw;
        if (it == 1) {
            const float* x0 = x + (row0 + g)*C_;
            const float* x1 = x0 + 8*C_;
            #pragma unroll
            for (int kc = 0; kc < 4; kc++) {
                int k0 = 16*kc + 2*t4;
                float2 l0 = *(const float2*)(x0 + k0);
                float2 h0 = *(const float2*)(x0 + k0 + 8);
                float2 l1 = *(const float2*)(x1 + k0);
                float2 h1 = *(const float2*)(x1 + k0 + 8);
                PACK2(a[kc][0], l0.y, l0.x);
                PACK2(a[kc][1], l1.y, l1.x);
                PACK2(a[kc][2], h0.y, h0.x);
                PACK2(a[kc][3], h1.y, h1.x);
            }
        }

        float acc[12][4];
        #pragma unroll
        for (int j = 0; j < 12; j++)
            #pragma unroll
            for (int q = 0; q < 4; q++) acc[j][q] = 0.f;

        #pragma unroll
        for (int kc = 0; kc < 4; kc++) {
            #pragma unroll
            for (int j = 0; j < 12; j++) {
                unsigned b0 = smw[(8*(jh + j) + g)*WST2 + 8*kc + t4];
                unsigned b1 = smw[(8*(jh + j) + g)*WST2 + 8*kc + t4 + 4];
                mma16(acc[j], a[kc][0], a[kc][1], a[kc][2], a[kc][3], b0, b1);
            }
        }

        const long r0 = row0 + g, r1 = r0 + 8;
        #pragma unroll
        for (int j = 0; j < 12; j++) {
            int jj = jh + j;
            unsigned* dst = (jj < 8) ? g_Qh : (jj < 16) ? g_Kh : g_Vh;
            float sc = (jj < 8) ? SCALE_LOG2 : 1.0f;
            int wd = 4*(jj & 7) + t4;
            unsigned w0, w1;
            PACK2(w0, acc[j][1]*sc, acc[j][0]*sc);
            PACK2(w1, acc[j][3]*sc, acc[j][2]*sc);
            dst[r0*32 + wd] = w0;
            dst[r1*32 + wd] = w1;
        }
    }
}

// ==== Kernel 2: flash attention — cp.async double-buffer, LDSM(+trans) B-frags ====
#define PREFETCH(KS, BUF) do {                                                      \
    unsigned kd = smbase + (BUF)*SSBW*4;                                            \
    unsigned vd = kd + 128*KST3*4;                                                  \
    _Pragma("unroll")                                                               \
    for (int i_ = 0; i_ < 2; i_++) {                                                \
        int l_ = tid + i_*512;                                                      \
        int slot_ = l_ >> 3, wg_ = (l_ & 7) << 2;                                   \
        long soff_ = (long)((KS)*128 + slot_)*rsw + wg_;                            \
        CPA16(kd + (slot_*KST3 + wg_)*4, Kg + soff_);                               \
        CPA16(vd + (slot_*KST3 + wg_)*4, Vg + soff_);                               \
    }                                                                               \
    asm volatile("cp.async.commit_group;");                                         \
} while (0)

__global__ __launch_bounds__(512, 1) void attn_kernel() {
    extern __shared__ unsigned smu[];

    const int tid  = threadIdx.x;
    const int wid  = tid >> 5, lane = tid & 31;
    const int g    = lane >> 2, t4 = lane & 3;
    const int mq   = lane >> 3, rr = lane & 7;
    const int blk  = blockIdx.x;
    const int qb   = (NQB - 1) - blk / (B_*NW_);   // heaviest first (LPT)
    const int w    = blk % (B_*NW_);
    const int b    = w / NW_, wi = w % NW_;

    int base, r;
    if      (wi < 4) { base = wi*2048;     r = 1; }
    else if (wi < 6) { base = (wi-4)*4096; r = 2; }
    else             { base = 0;           r = 4; }

    const unsigned* Qg = g_Qh + ((long)b*N_ + base)*32;
    const unsigned* Kg = g_Kh + ((long)b*N_ + base)*32;
    const unsigned* Vg = g_Vh + ((long)b*N_ + base)*32;
    const int rsw = r * 32;

    const unsigned smbase = (unsigned)__cvta_generic_to_shared(smu);
    // K LDSM (non-trans): rows = keys; lanes 0-15 rows, 16-31 col-offset
    const unsigned kaddr0 = smbase + (((mq >> 1)*8 + rr)*KST3)*4 + (mq & 1)*16;
    // V LDSM (trans): tiles (keys lo/hi) x (c-block lo/hi)
    const unsigned vaddr0 = smbase + 128*KST3*4 + (((mq & 1)*8 + rr)*KST3 + (mq >> 1)*4)*4;

    // ---- Q fragments: 16 rows per warp ----
    const int row0 = qb*QB_ROWS + 16*wid;
    unsigned qa[4][4];
    {
        const unsigned* q0 = Qg + (long)(row0 + g)*rsw;
        const unsigned* q1 = q0 + (long)8*rsw;
        #pragma unroll
        for (int kc = 0; kc < 4; kc++) {
            qa[kc][0] = q0[8*kc + t4];
            qa[kc][1] = q1[8*kc + t4];
            qa[kc][2] = q0[8*kc + t4 + 4];
            qa[kc][3] = q1[8*kc + t4 + 4];
        }
    }

    float oacc[8][4];
    float m0 = -1e30f, m1 = -1e30f, l0v = 0.f, l1v = 0.f;
    #pragma unroll
    for (int j = 0; j < 8; j++)
        #pragma unroll
        for (int q = 0; q < 4; q++) oacc[j][q] = 0.f;

    const int nks = 2*qb + 2;
    PREFETCH(0, 0);
    asm volatile("cp.async.wait_group 0;");
    __syncthreads();

    for (int ks = 0; ks < nks; ks++) {
        const int cur = ks & 1;
        const bool more = (ks + 1 < nks);
        if (more) PREFETCH(ks + 1, cur ^ 1);

        const unsigned kbuf = kaddr0 + cur*SSBW*4;
        const unsigned vbuf = vaddr0 + cur*SSBW*4;

        #pragma unroll
        for (int half = 0; half < 2; half++) {
            const int kbase = ks*128 + half*64;

            // ---- S = Q K^T ----
            float sacc[8][4];
            #pragma unroll
            for (int j = 0; j < 8; j++)
                #pragma unroll
                for (int q = 0; q < 4; q++) sacc[j][q] = 0.f;

            #pragma unroll
            for (int kc = 0; kc < 4; kc++) {
                #pragma unroll
                for (int jp = 0; jp < 4; jp++) {
                    unsigned b00, b01, b10, b11;
                    unsigned addr = kbuf + (((half*64 + 16*jp)*KST3 + 8*kc) << 2);
                    LDSM4(b00, b01, b10, b11, addr);
                    mma16(sacc[2*jp  ], qa[kc][0], qa[kc][1], qa[kc][2], qa[kc][3], b00, b01);
                    mma16(sacc[2*jp+1], qa[kc][0], qa[kc][1], qa[kc][2], qa[kc][3], b10, b11);
                }
            }

            // ---- causal mask ----
            if (ks >= 2*qb) {
                int r0_ = row0 + g, r1_ = r0_ + 8;
                #pragma unroll
                for (int j = 0; j < 8; j++) {
                    int k0 = kbase + 8*j + 2*t4, k1 = k0 + 1;
                    if (k0 > r0_) sacc[j][0] = -1e30f;
                    if (k1 > r0_) sacc[j][1] = -1e30f;
                    if (k0 > r1_) sacc[j][2] = -1e30f;
                    if (k1 > r1_) sacc[j][3] = -1e30f;
                }
            }

            // ---- online softmax (log2 domain) ----
            {
                float rm0 = -1e30f, rm1 = -1e30f;
                #pragma unroll
                for (int j = 0; j < 8; j++) {
                    rm0 = fmaxf(rm0, fmaxf(sacc[j][0], sacc[j][1]));
                    rm1 = fmaxf(rm1, fmaxf(sacc[j][2], sacc[j][3]));
                }
                rm0 = fmaxf(rm0, __shfl_xor_sync(0xffffffffu, rm0, 1));
                rm0 = fmaxf(rm0, __shfl_xor_sync(0xffffffffu, rm0, 2));
                rm1 = fmaxf(rm1, __shfl_xor_sync(0xffffffffu, rm1, 1));
                rm1 = fmaxf(rm1, __shfl_xor_sync(0xffffffffu, rm1, 2));
                float mn0 = fmaxf(m0, rm0), mn1 = fmaxf(m1, rm1);
                float c0 = ex2(m0 - mn0),   c1 = ex2(m1 - mn1);
                m0 = mn0; m1 = mn1;
                float rs0 = 0.f, rs1 = 0.f;
                #pragma unroll
                for (int j = 0; j < 8; j++) {
                    float p0 = ex2(sacc[j][0] - mn0); rs0 += p0; sacc[j][0] = p0;
                    float p1 = ex2(sacc[j][1] - mn0); rs0 += p1; sacc[j][1] = p1;
                    float p2 = ex2(sacc[j][2] - mn1); rs1 += p2; sacc[j][2] = p2;
                    float p3 = ex2(sacc[j][3] - mn1); rs1 += p3; sacc[j][3] = p3;
                }
                rs0 += __shfl_xor_sync(0xffffffffu, rs0, 1);
                rs0 += __shfl_xor_sync(0xffffffffu, rs0, 2);
                rs1 += __shfl_xor_sync(0xffffffffu, rs1, 1);
                rs1 += __shfl_xor_sync(0xffffffffu, rs1, 2);
                l0v = l0v*c0 + rs0;
                l1v = l1v*c1 + rs1;
                #pragma unroll
                for (int jv = 0; jv < 8; jv++) {
                    oacc[jv][0] *= c0; oacc[jv][1] *= c0;
                    oacc[jv][2] *= c1; oacc[jv][3] *= c1;
                }
            }

            // ---- O += P V : ldmatrix.trans on raw V rows ----
            #pragma unroll
            for (int u = 0; u < 4; u++) {
                unsigned a0, a1, a2, a3;
                PACK2(a0, sacc[2*u  ][1], sacc[2*u  ][0]);
                PACK2(a1, sacc[2*u  ][3], sacc[2*u  ][2]);
                PACK2(a2, sacc[2*u+1][1], sacc[2*u+1][0]);
                PACK2(a3, sacc[2*u+1][3], sacc[2*u+1][2]);
                const int kb = half*64 + 16*u;
                #pragma unroll
                for (int jvp = 0; jvp < 4; jvp++) {
                    unsigned r0v, r1v, r2v, r3v;
                    unsigned addr = vbuf + ((kb*KST3 + 8*jvp) << 2);
                    LDSM4T(r0v, r1v, r2v, r3v, addr);
                    mma16(oacc[2*jvp  ], a0, a1, a2, a3, r0v, r1v);
                    mma16(oacc[2*jvp+1], a0, a1, a2, a3, r2v, r3v);
                }
            }
        }

        if (more) asm volatile("cp.async.wait_group 0;");
        __syncthreads();
    }

    // ---- epilogue ----
    float* Og = g_O + (long)(b*NW_ + wi)*M_*C_;
    float* Dg = g_D + (long)(b*NW_ + wi)*M_;
    {
        int r0_ = row0 + g, r1_ = r0_ + 8;
        float i0 = 1.0f / l0v, i1 = 1.0f / l1v;
        #pragma unroll
        for (int jv = 0; jv < 8; jv++) {
            *(float2*)&Og[(long)r0_*C_ + 8*jv + 2*t4] =
                make_float2(oacc[jv][0]*i0, oacc[jv][1]*i0);
            *(float2*)&Og[(long)r1_*C_ + 8*jv + 2*t4] =
                make_float2(oacc[jv][2]*i1, oacc[jv][3]*i1);
        }
        if (t4 == 0) {
            Dg[r0_] = l0v * ex2(m0);
            Dg[r1_] = l1v * ex2(m1);
        }
    }
}

// ============================ Kernel 3: mix ============================
__global__ __launch_bounds__(256) void mix_kernel(float* __restrict__ out) {
    const int tid = threadIdx.x;
    const int c = tid & 63;
    const int gp = blockIdx.x*4 + (tid >> 6);
    const int b = gp >> 13;
    const int p = gp & (N_-1);

    int w0 = p >> 11, r0 = p & 2047;
    long i0 = (long)(b*NW_ + w0)*M_ + r0;
    float d0 = g_D[i0];
    float dsum = d0;
    float num  = d0 * g_O[i0*C_ + c];

    if ((p & 1) == 0) {
        int w1 = 4 + (p >> 12), r1 = (p & 4095) >> 1;
        long i1 = (long)(b*NW_ + w1)*M_ + r1;
        float d1 = g_D[i1];
        dsum += d1;
        num  += d1 * g_O[i1*C_ + c];
    }
    if ((p & 3) == 0) {
        long i2 = (long)(b*NW_ + 6)*M_ + (p >> 2);
        float d2 = g_D[i2];
        dsum += d2;
        num  += d2 * g_O[i2*C_ + c];
    }
    out[((long)b*N_ + p)*C_ + c] = num / dsum;
}

// =======================================================================
extern "C" void kernel_launch(void* const* d_in, const int* in_sizes, int n_in,
                              void* d_out, int out_size) {
    (void)in_sizes; (void)n_in; (void)out_size;
    const float* x  = (const float*)d_in[0];
    const float* Wq = (const float*)d_in[1];
    const float* Wk = (const float*)d_in[2];
    const float* Wv = (const float*)d_in[3];
    float* out = (float*)d_out;

    const int smem1 = 192*WST2*4;             // 27648 B
    const int smem2 = 2*SSBW*4;               // 73728 B
    cudaFuncSetAttribute(qkv_kernel,  cudaFuncAttributeMaxDynamicSharedMemorySize, smem1);
    cudaFuncSetAttribute(attn_kernel, cudaFuncAttributeMaxDynamicSharedMemorySize, smem2);

    qkv_kernel<<<(B_*N_)/256, 512, smem1>>>(x, Wq, Wk, Wv);
    attn_kernel<<<NQB * B_ * NW_, 512, smem2>>>();
    mix_kernel<<<(B_*N_)/4, 256>>>(out);
}

// round 16
// speedup vs baseline: 1.3193x; 1.0402x over previous
#include <cuda_runtime.h>
#include <cuda_fp16.h>

#define B_  4
#define N_  8192
#define C_  64
#define M_  2048
#define NW_ 7
#define QB_ROWS 256
#define NQB 8
#define KST3 36
#define WST2 36
#define OST 36           // qkv bounce stride (words)
#define SSBW (128*KST3*2)
#define SCALE_LOG2 0.18033688011112042f

__device__ unsigned g_Qh[B_*N_*32];
__device__ unsigned g_Kh[B_*N_*32];
__device__ unsigned g_Vh[B_*N_*32];
__device__ unsigned g_Oh[(long)B_*NW_*M_*32];   // fp16x2-packed O
__device__ float g_D[B_*NW_*M_];

__device__ __forceinline__ float ex2(float x) {
    float y; asm("ex2.approx.f32 %0, %1;" : "=f"(y) : "f"(x)); return y;
}
__device__ __forceinline__ void mma16(float d[4], unsigned a0, unsigned a1, unsigned a2,
                                      unsigned a3, unsigned b0, unsigned b1) {
    asm volatile("mma.sync.aligned.m16n8k16.row.col.f32.f16.f16.f32 "
        "{%0,%1,%2,%3},{%4,%5,%6,%7},{%8,%9},{%0,%1,%2,%3};"
        : "+f"(d[0]), "+f"(d[1]), "+f"(d[2]), "+f"(d[3])
        : "r"(a0), "r"(a1), "r"(a2), "r"(a3), "r"(b0), "r"(b1));
}
#define PACK2(D, HI, LO) asm("cvt.rn.f16x2.f32 %0, %1, %2;" : "=r"(D) : "f"(HI), "f"(LO))
#define LDSM4(R0, R1, R2, R3, ADDR) \
    asm volatile("ldmatrix.sync.aligned.m8n8.x4.shared.b16 {%0,%1,%2,%3}, [%4];" \
        : "=r"(R0), "=r"(R1), "=r"(R2), "=r"(R3) : "r"(ADDR))
#define LDSM4T(R0, R1, R2, R3, ADDR) \
    asm volatile("ldmatrix.sync.aligned.m8n8.x4.trans.shared.b16 {%0,%1,%2,%3}, [%4];" \
        : "=r"(R0), "=r"(R1), "=r"(R2), "=r"(R3) : "r"(ADDR))
#define CPA16(DST, SRC) \
    asm volatile("cp.async.cg.shared.global [%0], [%1], 16;" :: "r"(DST), "l"(SRC))

// ====== Kernel 1: QKV — fp16 TC + smem-bounced coalesced stores ======
__global__ __launch_bounds__(512) void qkv_kernel(const float* __restrict__ x,
                                                  const float* __restrict__ Wq,
                                                  const float* __restrict__ Wk,
                                                  const float* __restrict__ Wv) {
    extern __shared__ unsigned sm[];
    unsigned* smw  = sm;                 // Wt16[192][WST2]  (6912 words)
    unsigned* sout = sm + 192*WST2;      // bounce [3][128][OST] (13824 words)
    const int tid = threadIdx.x;
    const int wid = tid >> 5, lane = tid & 31;
    const int g = lane >> 2, t4 = lane & 3;
    const int rw = wid >> 1;
    const int jh = (wid & 1) * 12;

    // hoisted x loads for iteration 0
    unsigned a[4][4];
    {
        const long row0 = (long)blockIdx.x*256 + 16*rw;
        const float* x0 = x + (row0 + g)*C_;
        const float* x1 = x0 + 8*C_;
        #pragma unroll
        for (int kc = 0; kc < 4; kc++) {
            int k0 = 16*kc + 2*t4;
            float2 l0 = *(const float2*)(x0 + k0);
            float2 h0 = *(const float2*)(x0 + k0 + 8);
            float2 l1 = *(const float2*)(x1 + k0);
            float2 h1 = *(const float2*)(x1 + k0 + 8);
            PACK2(a[kc][0], l0.y, l0.x);
            PACK2(a[kc][1], l1.y, l1.x);
            PACK2(a[kc][2], h0.y, h0.x);
            PACK2(a[kc][3], h1.y, h1.x);
        }
    }

    const float* Wm[3] = {Wq, Wk, Wv};
    for (int idx = tid; idx < 192*32; idx += 512) {
        int w = idx / 192, nn = idx % 192;
        const float* Wsrc = Wm[nn >> 6];
        float lo = Wsrc[(2*w    )*64 + (nn & 63)];
        float hi = Wsrc[(2*w + 1)*64 + (nn & 63)];
        unsigned pw; PACK2(pw, hi, lo);
        smw[nn*WST2 + w] = pw;
    }
    __syncthreads();

    #pragma unroll
    for (int it = 0; it < 2; it++) {
        if (it == 1) {
            const long row0 = (long)blockIdx.x*256 + 128 + 16*rw;
            const float* x0 = x + (row0 + g)*C_;
            const float* x1 = x0 + 8*C_;
            #pragma unroll
            for (int kc = 0; kc < 4; kc++) {
                int k0 = 16*kc + 2*t4;
                float2 l0 = *(const float2*)(x0 + k0);
                float2 h0 = *(const float2*)(x0 + k0 + 8);
                float2 l1 = *(const float2*)(x1 + k0);
                float2 h1 = *(const float2*)(x1 + k0 + 8);
                PACK2(a[kc][0], l0.y, l0.x);
                PACK2(a[kc][1], l1.y, l1.x);
                PACK2(a[kc][2], h0.y, h0.x);
                PACK2(a[kc][3], h1.y, h1.x);
            }
        }

        float acc[12][4];
        #pragma unroll
        for (int j = 0; j < 12; j++)
            #pragma unroll
            for (int q = 0; q < 4; q++) acc[j][q] = 0.f;

        #pragma unroll
        for (int kc = 0; kc < 4; kc++) {
            #pragma unroll
            for (int j = 0; j < 12; j++) {
                unsigned b0 = smw[(8*(jh + j) + g)*WST2 + 8*kc + t4];
                unsigned b1 = smw[(8*(jh + j) + g)*WST2 + 8*kc + t4 + 4];
                mma16(acc[j], a[kc][0], a[kc][1], a[kc][2], a[kc][3], b0, b1);
            }
        }

        // bounce to smem (conflict-free: bank = 4g + t4 + const)
        const int loc0 = 16*rw + g;
        #pragma unroll
        for (int j = 0; j < 12; j++) {
            int jj = jh + j;
            int m = jj >> 3;
            float sc = (jj < 8) ? SCALE_LOG2 : 1.0f;
            int wd = 4*(jj & 7) + t4;
            unsigned w0, w1;
            PACK2(w0, acc[j][1]*sc, acc[j][0]*sc);
            PACK2(w1, acc[j][3]*sc, acc[j][2]*sc);
            sout[m*128*OST + loc0*OST + wd]       = w0;
            sout[m*128*OST + (loc0+8)*OST + wd]   = w1;
        }
        __syncthreads();

        // coalesced copy out: 3 x 128 rows x 8 uint4
        const long gr0 = (long)blockIdx.x*256 + it*128;
        #pragma unroll
        for (int i = 0; i < 6; i++) {
            int idx = tid + i*512;
            int m = idx >> 10, rem = idx & 1023;
            int row = rem >> 3, wg = (rem & 7) << 2;
            uint4 v = *(uint4*)&sout[m*128*OST + row*OST + wg];
            unsigned* dst = (m == 0) ? g_Qh : (m == 1) ? g_Kh : g_Vh;
            *(uint4*)&dst[(gr0 + row)*32 + wg] = v;
        }
        __syncthreads();
    }
}

// ==== Kernel 2: flash attention — cp.async double-buffer, LDSM(+trans), fp16 O out ====
#define PREFETCH(KS, BUF) do {                                                      \
    unsigned kd = smbase + (BUF)*SSBW*4;                                            \
    unsigned vd = kd + 128*KST3*4;                                                  \
    _Pragma("unroll")                                                               \
    for (int i_ = 0; i_ < 2; i_++) {                                                \
        int l_ = tid + i_*512;                                                      \
        int slot_ = l_ >> 3, wg_ = (l_ & 7) << 2;                                   \
        long soff_ = (long)((KS)*128 + slot_)*rsw + wg_;                            \
        CPA16(kd + (slot_*KST3 + wg_)*4, Kg + soff_);                               \
        CPA16(vd + (slot_*KST3 + wg_)*4, Vg + soff_);                               \
    }                                                                               \
    asm volatile("cp.async.commit_group;");                                         \
} while (0)

__global__ __launch_bounds__(512, 1) void attn_kernel() {
    extern __shared__ unsigned smu[];

    const int tid  = threadIdx.x;
    const int wid  = tid >> 5, lane = tid & 31;
    const int g    = lane >> 2, t4 = lane & 3;
    const int mq   = lane >> 3, rr = lane & 7;
    const int blk  = blockIdx.x;
    const int qb   = (NQB - 1) - blk / (B_*NW_);
    const int w    = blk % (B_*NW_);
    const int b    = w / NW_, wi = w % NW_;

    int base, r;
    if      (wi < 4) { base = wi*2048;     r = 1; }
    else if (wi < 6) { base = (wi-4)*4096; r = 2; }
    else             { base = 0;           r = 4; }

    const unsigned* Qg = g_Qh + ((long)b*N_ + base)*32;
    const unsigned* Kg = g_Kh + ((long)b*N_ + base)*32;
    const unsigned* Vg = g_Vh + ((long)b*N_ + base)*32;
    const int rsw = r * 32;

    const unsigned smbase = (unsigned)__cvta_generic_to_shared(smu);
    const unsigned kaddr0 = smbase + (((mq >> 1)*8 + rr)*KST3)*4 + (mq & 1)*16;
    const unsigned vaddr0 = smbase + 128*KST3*4 + (((mq & 1)*8 + rr)*KST3 + (mq >> 1)*4)*4;

    const int row0 = qb*QB_ROWS + 16*wid;
    unsigned qa[4][4];
    {
        const unsigned* q0 = Qg + (long)(row0 + g)*rsw;
        const unsigned* q1 = q0 + (long)8*rsw;
        #pragma unroll
        for (int kc = 0; kc < 4; kc++) {
            qa[kc][0] = q0[8*kc + t4];
            qa[kc][1] = q1[8*kc + t4];
            qa[kc][2] = q0[8*kc + t4 + 4];
            qa[kc][3] = q1[8*kc + t4 + 4];
        }
    }

    float oacc[8][4];
    float m0 = -1e30f, m1 = -1e30f, l0v = 0.f, l1v = 0.f;
    #pragma unroll
    for (int j = 0; j < 8; j++)
        #pragma unroll
        for (int q = 0; q < 4; q++) oacc[j][q] = 0.f;

    const int nks = 2*qb + 2;
    PREFETCH(0, 0);
    asm volatile("cp.async.wait_group 0;");
    __syncthreads();

    for (int ks = 0; ks < nks; ks++) {
        const int cur = ks & 1;
        const bool more = (ks + 1 < nks);
        if (more) PREFETCH(ks + 1, cur ^ 1);

        const unsigned kbuf = kaddr0 + cur*SSBW*4;
        const unsigned vbuf = vaddr0 + cur*SSBW*4;

        #pragma unroll
        for (int half = 0; half < 2; half++) {
            const int kbase = ks*128 + half*64;

            float sacc[8][4];
            #pragma unroll
            for (int j = 0; j < 8; j++)
                #pragma unroll
                for (int q = 0; q < 4; q++) sacc[j][q] = 0.f;

            #pragma unroll
            for (int kc = 0; kc < 4; kc++) {
                #pragma unroll
                for (int jp = 0; jp < 4; jp++) {
                    unsigned b00, b01, b10, b11;
                    unsigned addr = kbuf + (((half*64 + 16*jp)*KST3 + 8*kc) << 2);
                    LDSM4(b00, b01, b10, b11, addr);
                    mma16(sacc[2*jp  ], qa[kc][0], qa[kc][1], qa[kc][2], qa[kc][3], b00, b01);
                    mma16(sacc[2*jp+1], qa[kc][0], qa[kc][1], qa[kc][2], qa[kc][3], b10, b11);
                }
            }

            if (ks >= 2*qb) {
                int r0_ = row0 + g, r1_ = r0_ + 8;
                #pragma unroll
                for (int j = 0; j < 8; j++) {
                    int k0 = kbase + 8*j + 2*t4, k1 = k0 + 1;
                    if (k0 > r0_) sacc[j][0] = -1e30f;
                    if (k1 > r0_) sacc[j][1] = -1e30f;
                    if (k0 > r1_) sacc[j][2] = -1e30f;
                    if (k1 > r1_) sacc[j][3] = -1e30f;
                }
            }

            {
                float rm0 = -1e30f, rm1 = -1e30f;
                #pragma unroll
                for (int j = 0; j < 8; j++) {
                    rm0 = fmaxf(rm0, fmaxf(sacc[j][0], sacc[j][1]));
                    rm1 = fmaxf(rm1, fmaxf(sacc[j][2], sacc[j][3]));
                }
                rm0 = fmaxf(rm0, __shfl_xor_sync(0xffffffffu, rm0, 1));
                rm0 = fmaxf(rm0, __shfl_xor_sync(0xffffffffu, rm0, 2));
                rm1 = fmaxf(rm1, __shfl_xor_sync(0xffffffffu, rm1, 1));
                rm1 = fmaxf(rm1, __shfl_xor_sync(0xffffffffu, rm1, 2));
                float mn0 = fmaxf(m0, rm0), mn1 = fmaxf(m1, rm1);
                float c0 = ex2(m0 - mn0),   c1 = ex2(m1 - mn1);
                m0 = mn0; m1 = mn1;
                float rs0 = 0.f, rs1 = 0.f;
                #pragma unroll
                for (int j = 0; j < 8; j++) {
                    float p0 = ex2(sacc[j][0] - mn0); rs0 += p0; sacc[j][0] = p0;
                    float p1 = ex2(sacc[j][1] - mn0); rs0 += p1; sacc[j][1] = p1;
                    float p2 = ex2(sacc[j][2] - mn1); rs1 += p2; sacc[j][2] = p2;
                    float p3 = ex2(sacc[j][3] - mn1); rs1 += p3; sacc[j][3] = p3;
                }
                rs0 += __shfl_xor_sync(0xffffffffu, rs0, 1);
                rs0 += __shfl_xor_sync(0xffffffffu, rs0, 2);
                rs1 += __shfl_xor_sync(0xffffffffu, rs1, 1);
                rs1 += __shfl_xor_sync(0xffffffffu, rs1, 2);
                l0v = l0v*c0 + rs0;
                l1v = l1v*c1 + rs1;
                #pragma unroll
                for (int jv = 0; jv < 8; jv++) {
                    oacc[jv][0] *= c0; oacc[jv][1] *= c0;
                    oacc[jv][2] *= c1; oacc[jv][3] *= c1;
                }
            }

            #pragma unroll
            for (int u = 0; u < 4; u++) {
                unsigned a0, a1, a2, a3;
                PACK2(a0, sacc[2*u  ][1], sacc[2*u  ][0]);
                PACK2(a1, sacc[2*u  ][3], sacc[2*u  ][2]);
                PACK2(a2, sacc[2*u+1][1], sacc[2*u+1][0]);
                PACK2(a3, sacc[2*u+1][3], sacc[2*u+1][2]);
                const int kb = half*64 + 16*u;
                #pragma unroll
                for (int jvp = 0; jvp < 4; jvp++) {
                    unsigned r0v, r1v, r2v, r3v;
                    unsigned addr = vbuf + ((kb*KST3 + 8*jvp) << 2);
                    LDSM4T(r0v, r1v, r2v, r3v, addr);
                    mma16(oacc[2*jvp  ], a0, a1, a2, a3, r0v, r1v);
                    mma16(oacc[2*jvp+1], a0, a1, a2, a3, r2v, r3v);
                }
            }
        }

        if (more) asm volatile("cp.async.wait_group 0;");
        __syncthreads();
    }

    // ---- epilogue: packed fp16 O + denominator ----
    unsigned* Og = g_Oh + (long)(b*NW_ + wi)*M_*32;
    float* Dg = g_D + (long)(b*NW_ + wi)*M_;
    {
        int r0_ = row0 + g, r1_ = r0_ + 8;
        float i0 = 1.0f / l0v, i1 = 1.0f / l1v;
        #pragma unroll
        for (int jv = 0; jv < 8; jv++) {
            unsigned p0, p1;
            PACK2(p0, oacc[jv][1]*i0, oacc[jv][0]*i0);
            PACK2(p1, oacc[jv][3]*i1, oacc[jv][2]*i1);
            Og[(long)r0_*32 + 4*jv + t4] = p0;
            Og[(long)r1_*32 + 4*jv + t4] = p1;
        }
        if (t4 == 0) {
            Dg[r0_] = l0v * ex2(m0);
            Dg[r1_] = l1v * ex2(m1);
        }
    }
}

// ============ Kernel 3: mix — fp16 packed reads, float2 coalesced writes ============
__global__ __launch_bounds__(256) void mix_kernel(float* __restrict__ out) {
    const int tid = threadIdx.x;
    const int c2 = tid & 31;                 // word index = channel pair
    const int gp = blockIdx.x*8 + (tid >> 5);
    const int b = gp >> 13;
    const int p = gp & (N_-1);

    float nx = 0.f, ny = 0.f, dsum = 0.f;
    #define ACC1(SLOT, ROW) do {                                        \
        long i_ = ((long)b*NW_ + (SLOT))*M_ + (ROW);                    \
        float d_ = g_D[i_];                                             \
        unsigned w_ = g_Oh[i_*32 + c2];                                 \
        float2 f_ = __half22float2(*reinterpret_cast<__half2*>(&w_));   \
        dsum += d_;                                                     \
        nx += d_ * f_.x;                                                \
        ny += d_ * f_.y;                                                \
    } while (0)

    int w0 = p >> 11, r0 = p & 2047;
    ACC1(w0, r0);
    if ((p & 1) == 0) {
        int w1 = 4 + (p >> 12), r1 = (p & 4095) >> 1;
        ACC1(w1, r1);
    }
    if ((p & 3) == 0) {
        ACC1(6, p >> 2);
    }
    #undef ACC1
    float inv = 1.0f / dsum;
    *(float2*)&out[((long)b*N_ + p)*C_ + 2*c2] = make_float2(nx*inv, ny*inv);
}

// =======================================================================
extern "C" void kernel_launch(void* const* d_in, const int* in_sizes, int n_in,
                              void* d_out, int out_size) {
    (void)in_sizes; (void)n_in; (void)out_size;
    const float* x  = (const float*)d_in[0];
    const float* Wq = (const float*)d_in[1];
    const float* Wk = (const float*)d_in[2];
    const float* Wv = (const float*)d_in[3];
    float* out = (float*)d_out;

    const int smem1 = (192*WST2 + 3*128*OST) * 4;   // 82944 B
    const int smem2 = 2*SSBW*4;                     // 73728 B
    cudaFuncSetAttribute(qkv_kernel,  cudaFuncAttributeMaxDynamicSharedMemorySize, smem1);
    cudaFuncSetAttribute(attn_kernel, cudaFuncAttributeMaxDynamicSharedMemorySize, smem2);

    qkv_kernel<<<(B_*N_)/256, 512, smem1>>>(x, Wq, Wk, Wv);
    attn_kernel<<<NQB * B_ * NW_, 512, smem2>>>();
    mix_kernel<<<(B_*N_)/8, 256>>>(out);
}